// round 1
// baseline (speedup 1.0000x reference)
#include <cuda_runtime.h>
#include <cuda_bf16.h>
#include <math.h>

#define B_    4
#define S_    2048
#define D_    1024
#define H_    16
#define HD_   64
#define E_    8
#define F_    4096
#define FS_   2048
#define T_    8192
#define CAP_  2560
#define KT_   16384   // K * T slots

// ---------------- scratch (static device globals; no allocations) ----------
__device__ float g_xn1 [T_ * D_];
__device__ float g_q   [T_ * D_];
__device__ float g_k   [T_ * D_];
__device__ float g_v   [T_ * D_];
__device__ float g_attn[T_ * D_];
__device__ float g_x2  [T_ * D_];
__device__ float g_xn2 [T_ * D_];
__device__ float g_disp[E_ * CAP_ * D_];
__device__ float g_h   [E_ * CAP_ * F_];
__device__ float g_eo  [E_ * CAP_ * D_];
__device__ float g_shh [T_ * FS_];
__device__ float g_shout[T_ * D_];
__device__ int   g_eidx[KT_];
__device__ int   g_pos [KT_];
__device__ float g_gate[KT_];

// ---------------- LayerNorm: one block per row (D=1024, 256 thr x float4) --
__global__ void __launch_bounds__(256) ln_kernel(const float* __restrict__ x,
                                                 const float* __restrict__ g,
                                                 const float* __restrict__ b,
                                                 float* __restrict__ out)
{
    const int row = blockIdx.x;
    const int tid = threadIdx.x;
    const float4 v = ((const float4*)(x + (long)row * D_))[tid];

    __shared__ float red[256];
    __shared__ float s_mu, s_rstd;

    float s = v.x + v.y + v.z + v.w;
    red[tid] = s; __syncthreads();
    for (int o = 128; o > 0; o >>= 1) {
        if (tid < o) red[tid] += red[tid + o];
        __syncthreads();
    }
    if (tid == 0) s_mu = red[0] * (1.0f / D_);
    __syncthreads();
    const float mu = s_mu;

    float dx0 = v.x - mu, dx1 = v.y - mu, dx2 = v.z - mu, dx3 = v.w - mu;
    float sq = dx0*dx0 + dx1*dx1 + dx2*dx2 + dx3*dx3;
    red[tid] = sq; __syncthreads();
    for (int o = 128; o > 0; o >>= 1) {
        if (tid < o) red[tid] += red[tid + o];
        __syncthreads();
    }
    if (tid == 0) s_rstd = rsqrtf(red[0] * (1.0f / D_) + 1e-5f);
    __syncthreads();
    const float rstd = s_rstd;

    const float4 gg = ((const float4*)g)[tid];
    const float4 bb = ((const float4*)b)[tid];
    float4 o4;
    o4.x = dx0 * rstd * gg.x + bb.x;
    o4.y = dx1 * rstd * gg.y + bb.y;
    o4.z = dx2 * rstd * gg.z + bb.z;
    o4.w = dx3 * rstd * gg.w + bb.w;
    ((float4*)(out + (long)row * D_))[tid] = o4;
}

// ---------------- SGEMM: C = A[M,K] * B[K,N] + bias (+opt GELU, +opt res) --
// 128x128 block tile, BK=8, 256 threads, 8x8 per thread. All dims are
// multiples of 128/8 in this problem -> no bounds checks.
template<bool GELU, bool RES>
__global__ void __launch_bounds__(256) sgemm_kernel(
    const float* __restrict__ A, const float* __restrict__ Bm,
    const float* __restrict__ bias, const float* __restrict__ res,
    float* __restrict__ C, int M, int N, int Kd,
    long strideA, long strideB, long strideBias, long strideC)
{
    __shared__ float As[8][128];
    __shared__ float Bs[8][128];

    const int tid = threadIdx.x;
    const int bz = blockIdx.z;
    A  += (long)bz * strideA;
    Bm += (long)bz * strideB;
    bias += (long)bz * strideBias;
    C  += (long)bz * strideC;

    const int m0 = blockIdx.y * 128;
    const int n0 = blockIdx.x * 128;

    const int arow = tid >> 1, acol = (tid & 1) * 4;
    const int brow = tid >> 5, bcol = (tid & 31) * 4;
    const float* Aptr = A + (long)(m0 + arow) * Kd + acol;
    const float* Bptr = Bm + (long)brow * N + n0 + bcol;

    const int ty = tid >> 4, tx = tid & 15;
    float acc[8][8];
    #pragma unroll
    for (int i = 0; i < 8; i++)
        #pragma unroll
        for (int j = 0; j < 8; j++) acc[i][j] = 0.0f;

    for (int k0 = 0; k0 < Kd; k0 += 8) {
        float4 av = *(const float4*)Aptr;
        float4 bv = *(const float4*)Bptr;
        As[acol + 0][arow] = av.x;
        As[acol + 1][arow] = av.y;
        As[acol + 2][arow] = av.z;
        As[acol + 3][arow] = av.w;
        *(float4*)&Bs[brow][bcol] = bv;
        __syncthreads();

        #pragma unroll
        for (int kk = 0; kk < 8; kk++) {
            float4 a0 = *(const float4*)&As[kk][ty * 8];
            float4 a1 = *(const float4*)&As[kk][ty * 8 + 4];
            float4 b0 = *(const float4*)&Bs[kk][tx * 8];
            float4 b1 = *(const float4*)&Bs[kk][tx * 8 + 4];
            float a[8] = {a0.x, a0.y, a0.z, a0.w, a1.x, a1.y, a1.z, a1.w};
            float bq[8] = {b0.x, b0.y, b0.z, b0.w, b1.x, b1.y, b1.z, b1.w};
            #pragma unroll
            for (int i = 0; i < 8; i++)
                #pragma unroll
                for (int j = 0; j < 8; j++)
                    acc[i][j] += a[i] * bq[j];
        }
        __syncthreads();
        Aptr += 8;
        Bptr += (long)8 * N;
    }

    #pragma unroll
    for (int i = 0; i < 8; i++) {
        const int row = m0 + ty * 8 + i;
        #pragma unroll
        for (int j = 0; j < 8; j++) {
            const int col = n0 + tx * 8 + j;
            float c = acc[i][j] + bias[col];
            if (GELU) c = c * normcdff(c);   // exact gelu: x * Phi(x)
            if (RES)  c += res[(long)row * N + col];
            C[(long)row * N + col] = c;
        }
    }
}

// ---------------- Flash attention tile: 64 queries x (one b,h) ------------
// 256 threads as 16x16; each thread owns 4 queries x 4 dims / 4 keys.
#define ATT_SMEM (4 * 64 * 65 * 4)
__global__ void __launch_bounds__(256) attn_kernel(
    const float* __restrict__ qg, const float* __restrict__ kg,
    const float* __restrict__ vg, const unsigned char* __restrict__ maskg,
    float* __restrict__ og)
{
    extern __shared__ float sm[];
    float* Qs = sm;                // [64][65]
    float* Ks = Qs + 64 * 65;
    float* Vs = Ks + 64 * 65;
    float* Ps = Vs + 64 * 65;

    const int b = blockIdx.z, h = blockIdx.y, q0 = blockIdx.x * 64;
    const int tid = threadIdx.x;
    const int tx = tid & 15, ty = tid >> 4;
    const float scale = 0.125f;          // 1/sqrt(64)
    const float NEG = -3.402823466e38f;  // finfo(f32).min

    // load Q tile
    for (int i = tid; i < 1024; i += 256) {
        int r = i >> 4, c = (i & 15) << 2;
        float4 t4 = *(const float4*)&qg[((long)(b * S_ + q0 + r)) * D_ + h * 64 + c];
        float* d = &Qs[r * 65 + c];
        d[0] = t4.x; d[1] = t4.y; d[2] = t4.z; d[3] = t4.w;
    }

    float m[4], l[4], acc[4][4];
    #pragma unroll
    for (int i = 0; i < 4; i++) {
        m[i] = NEG; l[i] = 0.0f;
        #pragma unroll
        for (int j = 0; j < 4; j++) acc[i][j] = 0.0f;
    }

    for (int k0 = 0; k0 < S_; k0 += 64) {
        __syncthreads();  // protects Qs on first iter, Ks/Vs/Ps reuse afterwards
        for (int i = tid; i < 1024; i += 256) {
            int r = i >> 4, c = (i & 15) << 2;
            long base = ((long)(b * S_ + k0 + r)) * D_ + h * 64 + c;
            float4 k4 = *(const float4*)&kg[base];
            float4 v4 = *(const float4*)&vg[base];
            float* kd = &Ks[r * 65 + c];
            kd[0] = k4.x; kd[1] = k4.y; kd[2] = k4.z; kd[3] = k4.w;
            float* vd = &Vs[r * 65 + c];
            vd[0] = v4.x; vd[1] = v4.y; vd[2] = v4.z; vd[3] = v4.w;
        }
        __syncthreads();

        // S = Q K^T (4x4 per thread)
        float s[4][4];
        #pragma unroll
        for (int i = 0; i < 4; i++)
            #pragma unroll
            for (int j = 0; j < 4; j++) s[i][j] = 0.0f;
        #pragma unroll 8
        for (int d = 0; d < 64; d++) {
            float qa[4], kb[4];
            #pragma unroll
            for (int i = 0; i < 4; i++) qa[i] = Qs[(ty * 4 + i) * 65 + d];
            #pragma unroll
            for (int j = 0; j < 4; j++) kb[j] = Ks[(tx * 4 + j) * 65 + d];
            #pragma unroll
            for (int i = 0; i < 4; i++)
                #pragma unroll
                for (int j = 0; j < 4; j++) s[i][j] += qa[i] * kb[j];
        }
        // scale + mask
        bool msk[4];
        #pragma unroll
        for (int j = 0; j < 4; j++)
            msk[j] = maskg[b * S_ + k0 + tx * 4 + j] != 0;
        #pragma unroll
        for (int i = 0; i < 4; i++)
            #pragma unroll
            for (int j = 0; j < 4; j++)
                s[i][j] = msk[j] ? NEG : s[i][j] * scale;

        // online softmax update (row groups = 16 lanes sharing ty)
        float mnew[4], corr[4];
        #pragma unroll
        for (int i = 0; i < 4; i++) {
            float rmax = s[i][0];
            #pragma unroll
            for (int j = 1; j < 4; j++) rmax = fmaxf(rmax, s[i][j]);
            #pragma unroll
            for (int o = 1; o < 16; o <<= 1)
                rmax = fmaxf(rmax, __shfl_xor_sync(0xffffffffu, rmax, o));
            mnew[i] = fmaxf(m[i], rmax);
            corr[i] = expf(m[i] - mnew[i]);
            float rs = 0.0f;
            #pragma unroll
            for (int j = 0; j < 4; j++) {
                float p = expf(s[i][j] - mnew[i]);
                Ps[(ty * 4 + i) * 65 + tx * 4 + j] = p;
                rs += p;
            }
            #pragma unroll
            for (int o = 1; o < 16; o <<= 1)
                rs += __shfl_xor_sync(0xffffffffu, rs, o);
            l[i] = l[i] * corr[i] + rs;
            m[i] = mnew[i];
            #pragma unroll
            for (int j = 0; j < 4; j++) acc[i][j] *= corr[i];
        }
        __syncthreads();

        // acc += P V
        #pragma unroll 8
        for (int kk = 0; kk < 64; kk++) {
            float pp[4], vv[4];
            #pragma unroll
            for (int i = 0; i < 4; i++) pp[i] = Ps[(ty * 4 + i) * 65 + kk];
            #pragma unroll
            for (int j = 0; j < 4; j++) vv[j] = Vs[kk * 65 + tx * 4 + j];
            #pragma unroll
            for (int i = 0; i < 4; i++)
                #pragma unroll
                for (int j = 0; j < 4; j++) acc[i][j] += pp[i] * vv[j];
        }
    }

    #pragma unroll
    for (int i = 0; i < 4; i++) {
        const float inv = 1.0f / l[i];
        const long row = (long)(b * S_ + q0 + ty * 4 + i);
        #pragma unroll
        for (int j = 0; j < 4; j++)
            og[row * D_ + h * 64 + tx * 4 + j] = acc[i][j] * inv;
    }
}

// ---------------- Router: warp per token ----------------------------------
__global__ void __launch_bounds__(256) router_kernel(
    const float* __restrict__ xn, const float* __restrict__ wr,
    int* __restrict__ eidx, float* __restrict__ gate)
{
    const int warp = threadIdx.x >> 5, lane = threadIdx.x & 31;
    const int t = blockIdx.x * 8 + warp;
    const float* xr = xn + (long)t * D_;

    float a[E_];
    #pragma unroll
    for (int e = 0; e < E_; e++) a[e] = 0.0f;
    for (int d = lane; d < D_; d += 32) {
        const float xv = xr[d];
        const float* w = wr + d * E_;
        #pragma unroll
        for (int e = 0; e < E_; e++) a[e] += xv * w[e];
    }
    #pragma unroll
    for (int e = 0; e < E_; e++)
        #pragma unroll
        for (int o = 16; o > 0; o >>= 1)
            a[e] += __shfl_xor_sync(0xffffffffu, a[e], o);

    if (lane == 0) {
        float mx = a[0];
        #pragma unroll
        for (int e = 1; e < E_; e++) mx = fmaxf(mx, a[e]);
        float ex[E_];
        #pragma unroll
        for (int e = 0; e < E_; e++) ex[e] = expf(a[e] - mx);
        int i0 = 0; float v0 = ex[0];
        #pragma unroll
        for (int e = 1; e < E_; e++) if (ex[e] > v0) { v0 = ex[e]; i0 = e; }
        int i1 = -1; float v1 = -1.0f;
        #pragma unroll
        for (int e = 0; e < E_; e++)
            if (e != i0 && ex[e] > v1) { v1 = ex[e]; i1 = e; }
        const float inv = 1.0f / (v0 + v1);
        eidx[t]       = i0; gate[t]       = v0 * inv;
        eidx[T_ + t]  = i1; gate[T_ + t]  = v1 * inv;
    }
}

// ---------------- Slot-major capacity scan (deterministic, matches cumsum) -
__global__ void __launch_bounds__(256) scan_kernel(const int* __restrict__ eidx,
                                                   int* __restrict__ pos)
{
    const int e = blockIdx.x;
    __shared__ int sd[256];
    int base = 0;
    for (int c = 0; c < KT_; c += 256) {
        const int i = c + threadIdx.x;
        const int flag = (eidx[i] == e) ? 1 : 0;
        sd[threadIdx.x] = flag;
        __syncthreads();
        for (int o = 1; o < 256; o <<= 1) {
            int v = (threadIdx.x >= o) ? sd[threadIdx.x - o] : 0;
            __syncthreads();
            sd[threadIdx.x] += v;
            __syncthreads();
        }
        if (flag) pos[i] = base + sd[threadIdx.x] - 1;
        base += sd[255];
        __syncthreads();
    }
}

__global__ void __launch_bounds__(256) zero_kernel(float4* __restrict__ p, int n4)
{
    const int i = blockIdx.x * 256 + threadIdx.x;
    if (i < n4) p[i] = make_float4(0.f, 0.f, 0.f, 0.f);
}

__global__ void __launch_bounds__(256) dispatch_kernel(
    const float* __restrict__ xn, const int* __restrict__ eidx,
    const int* __restrict__ pos, float* __restrict__ disp)
{
    const int s = blockIdx.x;
    const int p = pos[s];
    if (p >= CAP_) return;
    const int e = eidx[s];
    const int t = s & (T_ - 1);
    const float4* src = (const float4*)(xn + (long)t * D_);
    float4* dst = (float4*)(disp + ((long)e * CAP_ + p) * D_);
    dst[threadIdx.x] = src[threadIdx.x];
}

__global__ void __launch_bounds__(256) combine_kernel(
    const float* __restrict__ x2, const float* __restrict__ shout,
    const float* __restrict__ eo, const int* __restrict__ eidx,
    const int* __restrict__ pos, const float* __restrict__ gate,
    float* __restrict__ out)
{
    const int t = blockIdx.x;
    const int p0 = pos[t], p1 = pos[T_ + t];
    const float g0 = gate[t]      * (p0 < CAP_ ? 1.0f : 0.0f);
    const float g1 = gate[T_ + t] * (p1 < CAP_ ? 1.0f : 0.0f);
    const long o0 = ((long)eidx[t]      * CAP_ + min(p0, CAP_ - 1)) * D_;
    const long o1 = ((long)eidx[T_ + t] * CAP_ + min(p1, CAP_ - 1)) * D_;

    const int c = threadIdx.x;
    float4 a = ((const float4*)(x2 + (long)t * D_))[c];
    float4 s = ((const float4*)(shout + (long)t * D_))[c];
    float4 r0 = ((const float4*)(eo + o0))[c];
    float4 r1 = ((const float4*)(eo + o1))[c];
    float4 o;
    o.x = a.x + s.x + g0 * r0.x + g1 * r1.x;
    o.y = a.y + s.y + g0 * r0.y + g1 * r1.y;
    o.z = a.z + s.z + g0 * r0.z + g1 * r1.z;
    o.w = a.w + s.w + g0 * r0.w + g1 * r1.w;
    ((float4*)(out + (long)t * D_))[c] = o;
}

// ---------------------------------------------------------------------------
extern "C" void kernel_launch(void* const* d_in, const int* in_sizes, int n_in,
                              void* d_out, int out_size)
{
    const float* x   = (const float*)d_in[0];
    const unsigned char* mask = (const unsigned char*)d_in[1];
    const float* ln1g = (const float*)d_in[2];
    const float* ln1b = (const float*)d_in[3];
    const float* wq = (const float*)d_in[4];  const float* bq = (const float*)d_in[5];
    const float* wk = (const float*)d_in[6];  const float* bk = (const float*)d_in[7];
    const float* wv = (const float*)d_in[8];  const float* bv = (const float*)d_in[9];
    const float* wo = (const float*)d_in[10]; const float* bo = (const float*)d_in[11];
    const float* ln2g = (const float*)d_in[12];
    const float* ln2b = (const float*)d_in[13];
    const float* wr = (const float*)d_in[14];
    const float* w1 = (const float*)d_in[15]; const float* b1 = (const float*)d_in[16];
    const float* w2 = (const float*)d_in[17]; const float* b2 = (const float*)d_in[18];
    const float* ws1 = (const float*)d_in[19]; const float* bs1 = (const float*)d_in[20];
    const float* ws2 = (const float*)d_in[21]; const float* bs2 = (const float*)d_in[22];
    float* out = (float*)d_out;

    float *xn1, *q, *k, *v, *attn, *x2, *xn2, *disp, *hb, *eo, *shh, *shout, *gate;
    int *eidx, *pos;
    cudaGetSymbolAddress((void**)&xn1,  g_xn1);
    cudaGetSymbolAddress((void**)&q,    g_q);
    cudaGetSymbolAddress((void**)&k,    g_k);
    cudaGetSymbolAddress((void**)&v,    g_v);
    cudaGetSymbolAddress((void**)&attn, g_attn);
    cudaGetSymbolAddress((void**)&x2,   g_x2);
    cudaGetSymbolAddress((void**)&xn2,  g_xn2);
    cudaGetSymbolAddress((void**)&disp, g_disp);
    cudaGetSymbolAddress((void**)&hb,   g_h);
    cudaGetSymbolAddress((void**)&eo,   g_eo);
    cudaGetSymbolAddress((void**)&shh,  g_shh);
    cudaGetSymbolAddress((void**)&shout,g_shout);
    cudaGetSymbolAddress((void**)&eidx, g_eidx);
    cudaGetSymbolAddress((void**)&pos,  g_pos);
    cudaGetSymbolAddress((void**)&gate, g_gate);

    cudaFuncSetAttribute(attn_kernel,
                         cudaFuncAttributeMaxDynamicSharedMemorySize, ATT_SMEM);

    // 1) LN1
    ln_kernel<<<T_, 256>>>(x, ln1g, ln1b, xn1);

    // 2) QKV projections
    dim3 gDD(D_ / 128, T_ / 128, 1);
    sgemm_kernel<false, false><<<gDD, 256>>>(xn1, wq, bq, nullptr, q, T_, D_, D_, 0, 0, 0, 0);
    sgemm_kernel<false, false><<<gDD, 256>>>(xn1, wk, bk, nullptr, k, T_, D_, D_, 0, 0, 0, 0);
    sgemm_kernel<false, false><<<gDD, 256>>>(xn1, wv, bv, nullptr, v, T_, D_, D_, 0, 0, 0, 0);

    // 3) attention
    attn_kernel<<<dim3(S_ / 64, H_, B_), 256, ATT_SMEM>>>(q, k, v, mask, attn);

    // 4) O projection + residual -> x2
    sgemm_kernel<false, true><<<gDD, 256>>>(attn, wo, bo, x, x2, T_, D_, D_, 0, 0, 0, 0);

    // 5) LN2
    ln_kernel<<<T_, 256>>>(x2, ln2g, ln2b, xn2);

    // 6) router + slot-major capacity scan
    router_kernel<<<T_ / 8, 256>>>(xn2, wr, eidx, gate);
    scan_kernel<<<E_, 256>>>(eidx, pos);

    // 7) dispatch
    const int n4 = E_ * CAP_ * D_ / 4;
    zero_kernel<<<(n4 + 255) / 256, 256>>>((float4*)disp, n4);
    dispatch_kernel<<<KT_, 256>>>(xn2, eidx, pos, disp);

    // 8) expert FFN (batched over blockIdx.z)
    sgemm_kernel<true, false><<<dim3(F_ / 128, CAP_ / 128, E_), 256>>>(
        disp, w1, b1, nullptr, hb, CAP_, F_, D_,
        (long)CAP_ * D_, (long)D_ * F_, (long)F_, (long)CAP_ * F_);
    sgemm_kernel<false, false><<<dim3(D_ / 128, CAP_ / 128, E_), 256>>>(
        hb, w2, b2, nullptr, eo, CAP_, D_, F_,
        (long)CAP_ * F_, (long)F_ * D_, (long)D_, (long)CAP_ * D_);

    // 9) shared expert
    sgemm_kernel<true, false><<<dim3(FS_ / 128, T_ / 128, 1), 256>>>(
        xn2, ws1, bs1, nullptr, shh, T_, FS_, D_, 0, 0, 0, 0);
    sgemm_kernel<false, false><<<dim3(D_ / 128, T_ / 128, 1), 256>>>(
        shh, ws2, bs2, nullptr, shout, T_, D_, FS_, 0, 0, 0, 0);

    // 10) combine + residuals -> out
    combine_kernel<<<T_, 256>>>(x2, shout, eo, eidx, pos, gate, out);
}

// round 4
// speedup vs baseline: 2.0054x; 2.0054x over previous
#include <cuda_runtime.h>
#include <cuda_bf16.h>
#include <math.h>
#include <stdint.h>

#define B_    4
#define S_    2048
#define D_    1024
#define H_    16
#define HD_   64
#define E_    8
#define F_    4096
#define FS_   2048
#define T_    8192
#define CAP_  2560
#define KT_   16384   // K * T slots

// ---------------- scratch (static device globals; no allocations) ----------
__device__ float g_xn1 [T_ * D_];
__device__ float g_q   [T_ * D_];
__device__ float g_k   [T_ * D_];
__device__ float g_v   [T_ * D_];
__device__ float g_attn[T_ * D_];
__device__ float g_x2  [T_ * D_];
__device__ float g_xn2 [T_ * D_];
__device__ float g_disp[E_ * CAP_ * D_];
__device__ float g_h   [E_ * CAP_ * F_];
__device__ float g_eo  [E_ * CAP_ * D_];
__device__ float g_shh [T_ * FS_];
__device__ float g_shout[T_ * D_];
__device__ int   g_eidx[KT_];
__device__ int   g_pos [KT_];
__device__ float g_gate[KT_];

// ---------------- helpers ---------------------------------------------------
// split x into hi (bf16) + lo (bf16 of residual); pack two elements per word
__device__ __forceinline__ void split2(float x, float y,
                                       uint32_t& hi, uint32_t& lo)
{
    __nv_bfloat16 hx = __float2bfloat16(x);
    __nv_bfloat16 hy = __float2bfloat16(y);
    float rx = x - __bfloat162float(hx);
    float ry = y - __bfloat162float(hy);
    __nv_bfloat162 h2; h2.x = hx; h2.y = hy;
    __nv_bfloat162 l2; l2.x = __float2bfloat16(rx); l2.y = __float2bfloat16(ry);
    hi = *(uint32_t*)&h2;
    lo = *(uint32_t*)&l2;
}

__device__ __forceinline__ void mma16(float* acc,
                                      uint32_t a0, uint32_t a1, uint32_t a2, uint32_t a3,
                                      uint32_t b0, uint32_t b1)
{
    asm volatile(
        "mma.sync.aligned.m16n8k16.row.col.f32.bf16.bf16.f32 "
        "{%0,%1,%2,%3},{%4,%5,%6,%7},{%8,%9},{%0,%1,%2,%3};"
        : "+f"(acc[0]), "+f"(acc[1]), "+f"(acc[2]), "+f"(acc[3])
        : "r"(a0), "r"(a1), "r"(a2), "r"(a3), "r"(b0), "r"(b1));
}

// ---------------- bf16x3 tensor-core GEMM ----------------------------------
// C[M,N] = A[M,K] @ B[K,N] + bias (+GELU) (+res). CTA 128x256, BK=32,
// 256 threads = 8 warps (2m x 4n), warp tile 64x64, m16n8k16 bf16 mma,
// 3-term split (hh + hl + lh) for ~fp32 accuracy.
#define APW 20      // A words (bf16x2 pairs) per row: 16 + 4 pad
#define BPW 264     // B words per kpair row: 256 + 8 pad
#define AW  (128 * APW)            // 2560 words per A plane
#define BW  (16 * BPW)             // 4224 words per B plane
#define BUFW (2 * AW + 2 * BW)     // 13568 words per buffer
#define TC_SMEM (2 * BUFW * 4)     // 108544 bytes

// plane offsets within a buffer (in words)
#define OF_AH 0
#define OF_AL AW
#define OF_BH (2 * AW)
#define OF_BL (2 * AW + BW)

__device__ __forceinline__ void kslice_mma(
    const uint32_t* __restrict__ buf, int kp0,
    int wm, int wn, int g, int t, float acc[4][8][4])
{
    const uint32_t* Ah = buf + OF_AH;
    const uint32_t* Al = buf + OF_AL;
    const uint32_t* Bh = buf + OF_BH;
    const uint32_t* Bl = buf + OF_BL;

    uint32_t bh[8][2], bl[8][2];
    #pragma unroll
    for (int nt = 0; nt < 8; nt++) {
        const int col = wn * 64 + nt * 8 + g;
        bh[nt][0] = Bh[(kp0 + t)     * BPW + col];
        bh[nt][1] = Bh[(kp0 + t + 4) * BPW + col];
        bl[nt][0] = Bl[(kp0 + t)     * BPW + col];
        bl[nt][1] = Bl[(kp0 + t + 4) * BPW + col];
    }
    #pragma unroll
    for (int mt = 0; mt < 4; mt++) {
        const int rb = wm * 64 + mt * 16 + g;
        const int i0 = rb * APW + kp0 + t;
        const int i1 = (rb + 8) * APW + kp0 + t;
        const uint32_t ah0 = Ah[i0],     ah1 = Ah[i1];
        const uint32_t ah2 = Ah[i0 + 4], ah3 = Ah[i1 + 4];
        const uint32_t al0 = Al[i0],     al1 = Al[i1];
        const uint32_t al2 = Al[i0 + 4], al3 = Al[i1 + 4];
        #pragma unroll
        for (int nt = 0; nt < 8; nt++) {
            mma16(acc[mt][nt], ah0, ah1, ah2, ah3, bh[nt][0], bh[nt][1]);
            mma16(acc[mt][nt], ah0, ah1, ah2, ah3, bl[nt][0], bl[nt][1]);
            mma16(acc[mt][nt], al0, al1, al2, al3, bh[nt][0], bh[nt][1]);
        }
    }
}

__device__ __forceinline__ void store_a(uint32_t* buf, int tid, const float4* ra)
{
    #pragma unroll
    for (int i = 0; i < 4; i++) {
        const int lin = i * 256 + tid;
        const int row = lin >> 3, kp = (lin & 7) * 2;
        uint32_t h0, l0, h1, l1;
        split2(ra[i].x, ra[i].y, h0, l0);
        split2(ra[i].z, ra[i].w, h1, l1);
        uint2 hv; hv.x = h0; hv.y = h1;
        uint2 lv; lv.x = l0; lv.y = l1;
        *(uint2*)&buf[OF_AH + row * APW + kp] = hv;
        *(uint2*)&buf[OF_AL + row * APW + kp] = lv;
    }
}
__device__ __forceinline__ void store_b2(uint32_t* buf, int tid, int ubase,
                                         const float4* r0, const float4* r1)
{
    #pragma unroll
    for (int u = 0; u < 2; u++) {
        const int lin = (ubase + u) * 256 + tid;
        const int kp = lin >> 6, nq = (lin & 63) * 4;
        uint32_t h[4], l[4];
        split2(r0[u].x, r1[u].x, h[0], l[0]);
        split2(r0[u].y, r1[u].y, h[1], l[1]);
        split2(r0[u].z, r1[u].z, h[2], l[2]);
        split2(r0[u].w, r1[u].w, h[3], l[3]);
        uint4 hv; hv.x = h[0]; hv.y = h[1]; hv.z = h[2]; hv.w = h[3];
        uint4 lv; lv.x = l[0]; lv.y = l[1]; lv.z = l[2]; lv.w = l[3];
        *(uint4*)&buf[OF_BH + kp * BPW + nq] = hv;
        *(uint4*)&buf[OF_BL + kp * BPW + nq] = lv;
    }
}

template<bool GELU, bool RES>
__global__ void __launch_bounds__(256) tc_gemm(
    const float* __restrict__ A, const float* __restrict__ Bw,
    const float* __restrict__ bias, const float* __restrict__ res,
    float* __restrict__ C, int Kd, int N,
    long sA, long sB, long sBias, long sC)
{
    extern __shared__ uint32_t smw[];
    const int tid = threadIdx.x, wid = tid >> 5, lane = tid & 31;
    const int g = lane >> 2, t = lane & 3;
    const int wm = wid & 1, wn = wid >> 1;
    const int bz = blockIdx.z;
    A += (long)bz * sA; Bw += (long)bz * sB; bias += (long)bz * sBias;
    C += (long)bz * sC;
    const int m0 = blockIdx.y * 128, n0 = blockIdx.x * 256;
    const int NT = Kd >> 5;

    float acc[4][8][4];
    #pragma unroll
    for (int mt = 0; mt < 4; mt++)
        #pragma unroll
        for (int nt = 0; nt < 8; nt++)
            #pragma unroll
            for (int c = 0; c < 4; c++) acc[mt][nt][c] = 0.0f;

    // ---- prologue: tile 0 into buffer 0 ----
    {
        float4 ra[4];
        #pragma unroll
        for (int i = 0; i < 4; i++) {
            const int lin = i * 256 + tid;
            const int row = lin >> 3, kq = (lin & 7) * 4;
            ra[i] = *(const float4*)(A + (long)(m0 + row) * Kd + kq);
        }
        store_a(smw, tid, ra);
        float4 r0[2], r1[2];
        #pragma unroll
        for (int ub = 0; ub < 4; ub += 2) {
            #pragma unroll
            for (int u = 0; u < 2; u++) {
                const int lin = (ub + u) * 256 + tid;
                const int kp = lin >> 6, nq = (lin & 63) * 4;
                r0[u] = *(const float4*)(Bw + (long)(2 * kp)     * N + n0 + nq);
                r1[u] = *(const float4*)(Bw + (long)(2 * kp + 1) * N + n0 + nq);
            }
            store_b2(smw, tid, ub, r0, r1);
        }
    }
    __syncthreads();

    for (int kt = 0; kt < NT; kt++) {
        const uint32_t* buf = smw + (kt & 1) * BUFW;
        uint32_t* nbuf = smw + ((kt + 1) & 1) * BUFW;
        const bool pf = (kt + 1 < NT);
        const int kb = (kt + 1) << 5;

        float4 ra[4], r0[2], r1[2];
        if (pf) {
            #pragma unroll
            for (int i = 0; i < 4; i++) {
                const int lin = i * 256 + tid;
                const int row = lin >> 3, kq = (lin & 7) * 4;
                ra[i] = *(const float4*)(A + (long)(m0 + row) * Kd + kb + kq);
            }
            #pragma unroll
            for (int u = 0; u < 2; u++) {
                const int lin = u * 256 + tid;
                const int kp = lin >> 6, nq = (lin & 63) * 4;
                r0[u] = *(const float4*)(Bw + (long)(kb + 2 * kp)     * N + n0 + nq);
                r1[u] = *(const float4*)(Bw + (long)(kb + 2 * kp + 1) * N + n0 + nq);
            }
        }

        kslice_mma(buf, 0, wm, wn, g, t, acc);

        if (pf) {
            store_a(nbuf, tid, ra);
            store_b2(nbuf, tid, 0, r0, r1);
            #pragma unroll
            for (int u = 0; u < 2; u++) {
                const int lin = (2 + u) * 256 + tid;
                const int kp = lin >> 6, nq = (lin & 63) * 4;
                r0[u] = *(const float4*)(Bw + (long)(kb + 2 * kp)     * N + n0 + nq);
                r1[u] = *(const float4*)(Bw + (long)(kb + 2 * kp + 1) * N + n0 + nq);
            }
        }

        kslice_mma(buf, 8, wm, wn, g, t, acc);

        if (pf) store_b2(nbuf, tid, 2, r0, r1);
        __syncthreads();
    }

    // ---- epilogue ----
    #pragma unroll
    for (int mt = 0; mt < 4; mt++) {
        const int row = m0 + wm * 64 + mt * 16 + g;
        #pragma unroll
        for (int nt = 0; nt < 8; nt++) {
            const int col = n0 + wn * 64 + nt * 8 + t * 2;
            const float b0v = bias[col], b1v = bias[col + 1];
            float v0 = acc[mt][nt][0] + b0v;
            float v1 = acc[mt][nt][1] + b1v;
            float v2 = acc[mt][nt][2] + b0v;
            float v3 = acc[mt][nt][3] + b1v;
            if (GELU) {
                v0 *= normcdff(v0); v1 *= normcdff(v1);
                v2 *= normcdff(v2); v3 *= normcdff(v3);
            }
            const long o0 = (long)row * N + col;
            const long o1 = (long)(row + 8) * N + col;
            if (RES) {
                const float2 r0 = *(const float2*)&res[o0];
                const float2 r1 = *(const float2*)&res[o1];
                v0 += r0.x; v1 += r0.y; v2 += r1.x; v3 += r1.y;
            }
            float2 w0; w0.x = v0; w0.y = v1;
            float2 w1; w1.x = v2; w1.y = v3;
            *(float2*)&C[o0] = w0;
            *(float2*)&C[o1] = w1;
        }
    }
}

// ---------------- LayerNorm -----------------------------------------------
__global__ void __launch_bounds__(256) ln_kernel(const float* __restrict__ x,
                                                 const float* __restrict__ g,
                                                 const float* __restrict__ b,
                                                 float* __restrict__ out)
{
    const int row = blockIdx.x;
    const int tid = threadIdx.x;
    const float4 v = ((const float4*)(x + (long)row * D_))[tid];

    __shared__ float red[256];
    __shared__ float s_mu, s_rstd;

    float s = v.x + v.y + v.z + v.w;
    red[tid] = s; __syncthreads();
    for (int o = 128; o > 0; o >>= 1) {
        if (tid < o) red[tid] += red[tid + o];
        __syncthreads();
    }
    if (tid == 0) s_mu = red[0] * (1.0f / D_);
    __syncthreads();
    const float mu = s_mu;

    float dx0 = v.x - mu, dx1 = v.y - mu, dx2 = v.z - mu, dx3 = v.w - mu;
    float sq = dx0*dx0 + dx1*dx1 + dx2*dx2 + dx3*dx3;
    red[tid] = sq; __syncthreads();
    for (int o = 128; o > 0; o >>= 1) {
        if (tid < o) red[tid] += red[tid + o];
        __syncthreads();
    }
    if (tid == 0) s_rstd = rsqrtf(red[0] * (1.0f / D_) + 1e-5f);
    __syncthreads();
    const float rstd = s_rstd;

    const float4 gg = ((const float4*)g)[tid];
    const float4 bb = ((const float4*)b)[tid];
    float4 o4;
    o4.x = dx0 * rstd * gg.x + bb.x;
    o4.y = dx1 * rstd * gg.y + bb.y;
    o4.z = dx2 * rstd * gg.z + bb.z;
    o4.w = dx3 * rstd * gg.w + bb.w;
    ((float4*)(out + (long)row * D_))[tid] = o4;
}

// ---------------- Flash attention tile (fp32 SIMT) ------------------------
#define ATT_SMEM (4 * 64 * 65 * 4)
__global__ void __launch_bounds__(256) attn_kernel(
    const float* __restrict__ qg, const float* __restrict__ kg,
    const float* __restrict__ vg, const unsigned char* __restrict__ maskg,
    float* __restrict__ og)
{
    extern __shared__ float sm[];
    float* Qs = sm;
    float* Ks = Qs + 64 * 65;
    float* Vs = Ks + 64 * 65;
    float* Ps = Vs + 64 * 65;

    const int b = blockIdx.z, h = blockIdx.y, q0 = blockIdx.x * 64;
    const int tid = threadIdx.x;
    const int tx = tid & 15, ty = tid >> 4;
    const float scale = 0.125f;
    const float NEG = -3.402823466e38f;

    for (int i = tid; i < 1024; i += 256) {
        int r = i >> 4, c = (i & 15) << 2;
        float4 t4 = *(const float4*)&qg[((long)(b * S_ + q0 + r)) * D_ + h * 64 + c];
        float* d = &Qs[r * 65 + c];
        d[0] = t4.x; d[1] = t4.y; d[2] = t4.z; d[3] = t4.w;
    }

    float m[4], l[4], acc[4][4];
    #pragma unroll
    for (int i = 0; i < 4; i++) {
        m[i] = NEG; l[i] = 0.0f;
        #pragma unroll
        for (int j = 0; j < 4; j++) acc[i][j] = 0.0f;
    }

    for (int k0 = 0; k0 < S_; k0 += 64) {
        __syncthreads();
        for (int i = tid; i < 1024; i += 256) {
            int r = i >> 4, c = (i & 15) << 2;
            long base = ((long)(b * S_ + k0 + r)) * D_ + h * 64 + c;
            float4 k4 = *(const float4*)&kg[base];
            float4 v4 = *(const float4*)&vg[base];
            float* kd = &Ks[r * 65 + c];
            kd[0] = k4.x; kd[1] = k4.y; kd[2] = k4.z; kd[3] = k4.w;
            float* vd = &Vs[r * 65 + c];
            vd[0] = v4.x; vd[1] = v4.y; vd[2] = v4.z; vd[3] = v4.w;
        }
        __syncthreads();

        float s[4][4];
        #pragma unroll
        for (int i = 0; i < 4; i++)
            #pragma unroll
            for (int j = 0; j < 4; j++) s[i][j] = 0.0f;
        #pragma unroll 8
        for (int d = 0; d < 64; d++) {
            float qa[4], kb[4];
            #pragma unroll
            for (int i = 0; i < 4; i++) qa[i] = Qs[(ty * 4 + i) * 65 + d];
            #pragma unroll
            for (int j = 0; j < 4; j++) kb[j] = Ks[(tx * 4 + j) * 65 + d];
            #pragma unroll
            for (int i = 0; i < 4; i++)
                #pragma unroll
                for (int j = 0; j < 4; j++) s[i][j] += qa[i] * kb[j];
        }
        bool msk[4];
        #pragma unroll
        for (int j = 0; j < 4; j++)
            msk[j] = maskg[b * S_ + k0 + tx * 4 + j] != 0;
        #pragma unroll
        for (int i = 0; i < 4; i++)
            #pragma unroll
            for (int j = 0; j < 4; j++)
                s[i][j] = msk[j] ? NEG : s[i][j] * scale;

        float mnew[4], corr[4];
        #pragma unroll
        for (int i = 0; i < 4; i++) {
            float rmax = s[i][0];
            #pragma unroll
            for (int j = 1; j < 4; j++) rmax = fmaxf(rmax, s[i][j]);
            #pragma unroll
            for (int o = 1; o < 16; o <<= 1)
                rmax = fmaxf(rmax, __shfl_xor_sync(0xffffffffu, rmax, o));
            mnew[i] = fmaxf(m[i], rmax);
            corr[i] = expf(m[i] - mnew[i]);
            float rs = 0.0f;
            #pragma unroll
            for (int j = 0; j < 4; j++) {
                float p = expf(s[i][j] - mnew[i]);
                Ps[(ty * 4 + i) * 65 + tx * 4 + j] = p;
                rs += p;
            }
            #pragma unroll
            for (int o = 1; o < 16; o <<= 1)
                rs += __shfl_xor_sync(0xffffffffu, rs, o);
            l[i] = l[i] * corr[i] + rs;
            m[i] = mnew[i];
            #pragma unroll
            for (int j = 0; j < 4; j++) acc[i][j] *= corr[i];
        }
        __syncthreads();

        #pragma unroll 8
        for (int kk = 0; kk < 64; kk++) {
            float pp[4], vv[4];
            #pragma unroll
            for (int i = 0; i < 4; i++) pp[i] = Ps[(ty * 4 + i) * 65 + kk];
            #pragma unroll
            for (int j = 0; j < 4; j++) vv[j] = Vs[kk * 65 + tx * 4 + j];
            #pragma unroll
            for (int i = 0; i < 4; i++)
                #pragma unroll
                for (int j = 0; j < 4; j++) acc[i][j] += pp[i] * vv[j];
        }
    }

    #pragma unroll
    for (int i = 0; i < 4; i++) {
        const float inv = 1.0f / l[i];
        const long row = (long)(b * S_ + q0 + ty * 4 + i);
        #pragma unroll
        for (int j = 0; j < 4; j++)
            og[row * D_ + h * 64 + tx * 4 + j] = acc[i][j] * inv;
    }
}

// ---------------- Router --------------------------------------------------
__global__ void __launch_bounds__(256) router_kernel(
    const float* __restrict__ xn, const float* __restrict__ wr,
    int* __restrict__ eidx, float* __restrict__ gate)
{
    const int warp = threadIdx.x >> 5, lane = threadIdx.x & 31;
    const int t = blockIdx.x * 8 + warp;
    const float* xr = xn + (long)t * D_;

    float a[E_];
    #pragma unroll
    for (int e = 0; e < E_; e++) a[e] = 0.0f;
    for (int d = lane; d < D_; d += 32) {
        const float xv = xr[d];
        const float* w = wr + d * E_;
        #pragma unroll
        for (int e = 0; e < E_; e++) a[e] += xv * w[e];
    }
    #pragma unroll
    for (int e = 0; e < E_; e++)
        #pragma unroll
        for (int o = 16; o > 0; o >>= 1)
            a[e] += __shfl_xor_sync(0xffffffffu, a[e], o);

    if (lane == 0) {
        float mx = a[0];
        #pragma unroll
        for (int e = 1; e < E_; e++) mx = fmaxf(mx, a[e]);
        float ex[E_];
        #pragma unroll
        for (int e = 0; e < E_; e++) ex[e] = expf(a[e] - mx);
        int i0 = 0; float v0 = ex[0];
        #pragma unroll
        for (int e = 1; e < E_; e++) if (ex[e] > v0) { v0 = ex[e]; i0 = e; }
        int i1 = -1; float v1 = -1.0f;
        #pragma unroll
        for (int e = 0; e < E_; e++)
            if (e != i0 && ex[e] > v1) { v1 = ex[e]; i1 = e; }
        const float inv = 1.0f / (v0 + v1);
        eidx[t]       = i0; gate[t]       = v0 * inv;
        eidx[T_ + t]  = i1; gate[T_ + t]  = v1 * inv;
    }
}

// ---------------- Slot-major capacity scan --------------------------------
__global__ void __launch_bounds__(256) scan_kernel(const int* __restrict__ eidx,
                                                   int* __restrict__ pos)
{
    const int e = blockIdx.x;
    __shared__ int sd[256];
    int base = 0;
    for (int c = 0; c < KT_; c += 256) {
        const int i = c + threadIdx.x;
        const int flag = (eidx[i] == e) ? 1 : 0;
        sd[threadIdx.x] = flag;
        __syncthreads();
        for (int o = 1; o < 256; o <<= 1) {
            int v = (threadIdx.x >= o) ? sd[threadIdx.x - o] : 0;
            __syncthreads();
            sd[threadIdx.x] += v;
            __syncthreads();
        }
        if (flag) pos[i] = base + sd[threadIdx.x] - 1;
        base += sd[255];
        __syncthreads();
    }
}

__global__ void __launch_bounds__(256) zero_kernel(float4* __restrict__ p, int n4)
{
    const int i = blockIdx.x * 256 + threadIdx.x;
    if (i < n4) p[i] = make_float4(0.f, 0.f, 0.f, 0.f);
}

__global__ void __launch_bounds__(256) dispatch_kernel(
    const float* __restrict__ xn, const int* __restrict__ eidx,
    const int* __restrict__ pos, float* __restrict__ disp)
{
    const int s = blockIdx.x;
    const int p = pos[s];
    if (p >= CAP_) return;
    const int e = eidx[s];
    const int t = s & (T_ - 1);
    const float4* src = (const float4*)(xn + (long)t * D_);
    float4* dst = (float4*)(disp + ((long)e * CAP_ + p) * D_);
    dst[threadIdx.x] = src[threadIdx.x];
}

__global__ void __launch_bounds__(256) combine_kernel(
    const float* __restrict__ x2, const float* __restrict__ shout,
    const float* __restrict__ eo, const int* __restrict__ eidx,
    const int* __restrict__ pos, const float* __restrict__ gate,
    float* __restrict__ out)
{
    const int t = blockIdx.x;
    const int p0 = pos[t], p1 = pos[T_ + t];
    const float g0 = gate[t]      * (p0 < CAP_ ? 1.0f : 0.0f);
    const float g1 = gate[T_ + t] * (p1 < CAP_ ? 1.0f : 0.0f);
    const long o0 = ((long)eidx[t]      * CAP_ + min(p0, CAP_ - 1)) * D_;
    const long o1 = ((long)eidx[T_ + t] * CAP_ + min(p1, CAP_ - 1)) * D_;

    const int c = threadIdx.x;
    float4 a = ((const float4*)(x2 + (long)t * D_))[c];
    float4 s = ((const float4*)(shout + (long)t * D_))[c];
    float4 r0 = ((const float4*)(eo + o0))[c];
    float4 r1 = ((const float4*)(eo + o1))[c];
    float4 o;
    o.x = a.x + s.x + g0 * r0.x + g1 * r1.x;
    o.y = a.y + s.y + g0 * r0.y + g1 * r1.y;
    o.z = a.z + s.z + g0 * r0.z + g1 * r1.z;
    o.w = a.w + s.w + g0 * r0.w + g1 * r1.w;
    ((float4*)(out + (long)t * D_))[c] = o;
}

// ---------------------------------------------------------------------------
extern "C" void kernel_launch(void* const* d_in, const int* in_sizes, int n_in,
                              void* d_out, int out_size)
{
    const float* x   = (const float*)d_in[0];
    const unsigned char* mask = (const unsigned char*)d_in[1];
    const float* ln1g = (const float*)d_in[2];
    const float* ln1b = (const float*)d_in[3];
    const float* wq = (const float*)d_in[4];  const float* bq = (const float*)d_in[5];
    const float* wk = (const float*)d_in[6];  const float* bk = (const float*)d_in[7];
    const float* wv = (const float*)d_in[8];  const float* bv = (const float*)d_in[9];
    const float* wo = (const float*)d_in[10]; const float* bo = (const float*)d_in[11];
    const float* ln2g = (const float*)d_in[12];
    const float* ln2b = (const float*)d_in[13];
    const float* wr = (const float*)d_in[14];
    const float* w1 = (const float*)d_in[15]; const float* b1 = (const float*)d_in[16];
    const float* w2 = (const float*)d_in[17]; const float* b2 = (const float*)d_in[18];
    const float* ws1 = (const float*)d_in[19]; const float* bs1 = (const float*)d_in[20];
    const float* ws2 = (const float*)d_in[21]; const float* bs2 = (const float*)d_in[22];
    float* out = (float*)d_out;

    float *xn1, *q, *k, *v, *attn, *x2, *xn2, *disp, *hb, *eo, *shh, *shout, *gate;
    int *eidx, *pos;
    cudaGetSymbolAddress((void**)&xn1,  g_xn1);
    cudaGetSymbolAddress((void**)&q,    g_q);
    cudaGetSymbolAddress((void**)&k,    g_k);
    cudaGetSymbolAddress((void**)&v,    g_v);
    cudaGetSymbolAddress((void**)&attn, g_attn);
    cudaGetSymbolAddress((void**)&x2,   g_x2);
    cudaGetSymbolAddress((void**)&xn2,  g_xn2);
    cudaGetSymbolAddress((void**)&disp, g_disp);
    cudaGetSymbolAddress((void**)&hb,   g_h);
    cudaGetSymbolAddress((void**)&eo,   g_eo);
    cudaGetSymbolAddress((void**)&shh,  g_shh);
    cudaGetSymbolAddress((void**)&shout,g_shout);
    cudaGetSymbolAddress((void**)&eidx, g_eidx);
    cudaGetSymbolAddress((void**)&pos,  g_pos);
    cudaGetSymbolAddress((void**)&gate, g_gate);

    cudaFuncSetAttribute(attn_kernel,
                         cudaFuncAttributeMaxDynamicSharedMemorySize, ATT_SMEM);
    cudaFuncSetAttribute(tc_gemm<false, false>,
                         cudaFuncAttributeMaxDynamicSharedMemorySize, TC_SMEM);
    cudaFuncSetAttribute(tc_gemm<false, true>,
                         cudaFuncAttributeMaxDynamicSharedMemorySize, TC_SMEM);
    cudaFuncSetAttribute(tc_gemm<true, false>,
                         cudaFuncAttributeMaxDynamicSharedMemorySize, TC_SMEM);

    // 1) LN1
    ln_kernel<<<T_, 256>>>(x, ln1g, ln1b, xn1);

    // 2) QKV projections (bf16x3 tensor cores)
    dim3 gDD(D_ / 256, T_ / 128, 1);
    tc_gemm<false, false><<<gDD, 256, TC_SMEM>>>(xn1, wq, bq, nullptr, q, D_, D_, 0, 0, 0, 0);
    tc_gemm<false, false><<<gDD, 256, TC_SMEM>>>(xn1, wk, bk, nullptr, k, D_, D_, 0, 0, 0, 0);
    tc_gemm<false, false><<<gDD, 256, TC_SMEM>>>(xn1, wv, bv, nullptr, v, D_, D_, 0, 0, 0, 0);

    // 3) attention
    attn_kernel<<<dim3(S_ / 64, H_, B_), 256, ATT_SMEM>>>(q, k, v, mask, attn);

    // 4) O projection + residual -> x2
    tc_gemm<false, true><<<gDD, 256, TC_SMEM>>>(attn, wo, bo, x, x2, D_, D_, 0, 0, 0, 0);

    // 5) LN2
    ln_kernel<<<T_, 256>>>(x2, ln2g, ln2b, xn2);

    // 6) router + slot-major capacity scan
    router_kernel<<<T_ / 8, 256>>>(xn2, wr, eidx, gate);
    scan_kernel<<<E_, 256>>>(eidx, pos);

    // 7) dispatch
    const int n4 = E_ * CAP_ * D_ / 4;
    zero_kernel<<<(n4 + 255) / 256, 256>>>((float4*)disp, n4);
    dispatch_kernel<<<KT_, 256>>>(xn2, eidx, pos, disp);

    // 8) expert FFN (batched over blockIdx.z = expert)
    tc_gemm<true, false><<<dim3(F_ / 256, CAP_ / 128, E_), 256, TC_SMEM>>>(
        disp, w1, b1, nullptr, hb, D_, F_,
        (long)CAP_ * D_, (long)D_ * F_, (long)F_, (long)CAP_ * F_);
    tc_gemm<false, false><<<dim3(D_ / 256, CAP_ / 128, E_), 256, TC_SMEM>>>(
        hb, w2, b2, nullptr, eo, F_, D_,
        (long)CAP_ * F_, (long)F_ * D_, (long)D_, (long)CAP_ * D_);

    // 9) shared expert
    tc_gemm<true, false><<<dim3(FS_ / 256, T_ / 128, 1), 256, TC_SMEM>>>(
        xn2, ws1, bs1, nullptr, shh, D_, FS_, 0, 0, 0, 0);
    tc_gemm<false, false><<<dim3(D_ / 256, T_ / 128, 1), 256, TC_SMEM>>>(
        shh, ws2, bs2, nullptr, shout, FS_, D_, 0, 0, 0, 0);

    // 10) combine + residuals -> out
    combine_kernel<<<T_, 256>>>(x2, shout, eo, eidx, pos, gate, out);
}

// round 5
// speedup vs baseline: 2.4607x; 1.2271x over previous
#include <cuda_runtime.h>
#include <cuda_bf16.h>
#include <math.h>
#include <stdint.h>

#define B_    4
#define S_    2048
#define D_    1024
#define H_    16
#define HD_   64
#define E_    8
#define F_    4096
#define FS_   2048
#define T_    8192
#define CAP_  2560
#define KT_   16384   // K * T slots

// ---------------- scratch (static device globals; no allocations) ----------
__device__ float g_xn1 [T_ * D_];
__device__ float g_q   [T_ * D_];
__device__ float g_k   [T_ * D_];
__device__ float g_v   [T_ * D_];
__device__ float g_vt  [T_ * D_];   // V transposed per (b,h): [b][h][hd][s]
__device__ float g_attn[T_ * D_];
__device__ float g_x2  [T_ * D_];
__device__ float g_xn2 [T_ * D_];
__device__ float g_disp[E_ * CAP_ * D_];
__device__ float g_h   [E_ * CAP_ * F_];
__device__ float g_eo  [E_ * CAP_ * D_];
__device__ float g_shh [T_ * FS_];
__device__ float g_shout[T_ * D_];
__device__ int   g_eidx[KT_];
__device__ int   g_pos [KT_];
__device__ float g_gate[KT_];

// ---------------- helpers ---------------------------------------------------
// split x into hi (bf16) + lo (bf16 of residual); pack two elements per word
__device__ __forceinline__ void split2(float x, float y,
                                       uint32_t& hi, uint32_t& lo)
{
    __nv_bfloat16 hx = __float2bfloat16(x);
    __nv_bfloat16 hy = __float2bfloat16(y);
    float rx = x - __bfloat162float(hx);
    float ry = y - __bfloat162float(hy);
    __nv_bfloat162 h2; h2.x = hx; h2.y = hy;
    __nv_bfloat162 l2; l2.x = __float2bfloat16(rx); l2.y = __float2bfloat16(ry);
    hi = *(uint32_t*)&h2;
    lo = *(uint32_t*)&l2;
}

__device__ __forceinline__ void mma16(float* acc,
                                      uint32_t a0, uint32_t a1, uint32_t a2, uint32_t a3,
                                      uint32_t b0, uint32_t b1)
{
    asm volatile(
        "mma.sync.aligned.m16n8k16.row.col.f32.bf16.bf16.f32 "
        "{%0,%1,%2,%3},{%4,%5,%6,%7},{%8,%9},{%0,%1,%2,%3};"
        : "+f"(acc[0]), "+f"(acc[1]), "+f"(acc[2]), "+f"(acc[3])
        : "r"(a0), "r"(a1), "r"(a2), "r"(a3), "r"(b0), "r"(b1));
}

// ---------------- bf16x3 tensor-core GEMM ----------------------------------
#define APW 20
#define BPW 264
#define AW  (128 * APW)
#define BW  (16 * BPW)
#define BUFW (2 * AW + 2 * BW)
#define TC_SMEM (2 * BUFW * 4)

#define OF_AH 0
#define OF_AL AW
#define OF_BH (2 * AW)
#define OF_BL (2 * AW + BW)

__device__ __forceinline__ void kslice_mma(
    const uint32_t* __restrict__ buf, int kp0,
    int wm, int wn, int g, int t, float acc[4][8][4])
{
    const uint32_t* Ah = buf + OF_AH;
    const uint32_t* Al = buf + OF_AL;
    const uint32_t* Bh = buf + OF_BH;
    const uint32_t* Bl = buf + OF_BL;

    uint32_t bh[8][2], bl[8][2];
    #pragma unroll
    for (int nt = 0; nt < 8; nt++) {
        const int col = wn * 64 + nt * 8 + g;
        bh[nt][0] = Bh[(kp0 + t)     * BPW + col];
        bh[nt][1] = Bh[(kp0 + t + 4) * BPW + col];
        bl[nt][0] = Bl[(kp0 + t)     * BPW + col];
        bl[nt][1] = Bl[(kp0 + t + 4) * BPW + col];
    }
    #pragma unroll
    for (int mt = 0; mt < 4; mt++) {
        const int rb = wm * 64 + mt * 16 + g;
        const int i0 = rb * APW + kp0 + t;
        const int i1 = (rb + 8) * APW + kp0 + t;
        const uint32_t ah0 = Ah[i0],     ah1 = Ah[i1];
        const uint32_t ah2 = Ah[i0 + 4], ah3 = Ah[i1 + 4];
        const uint32_t al0 = Al[i0],     al1 = Al[i1];
        const uint32_t al2 = Al[i0 + 4], al3 = Al[i1 + 4];
        #pragma unroll
        for (int nt = 0; nt < 8; nt++) {
            mma16(acc[mt][nt], ah0, ah1, ah2, ah3, bh[nt][0], bh[nt][1]);
            mma16(acc[mt][nt], ah0, ah1, ah2, ah3, bl[nt][0], bl[nt][1]);
            mma16(acc[mt][nt], al0, al1, al2, al3, bh[nt][0], bh[nt][1]);
        }
    }
}

__device__ __forceinline__ void store_a(uint32_t* buf, int tid, const float4* ra)
{
    #pragma unroll
    for (int i = 0; i < 4; i++) {
        const int lin = i * 256 + tid;
        const int row = lin >> 3, kp = (lin & 7) * 2;
        uint32_t h0, l0, h1, l1;
        split2(ra[i].x, ra[i].y, h0, l0);
        split2(ra[i].z, ra[i].w, h1, l1);
        uint2 hv; hv.x = h0; hv.y = h1;
        uint2 lv; lv.x = l0; lv.y = l1;
        *(uint2*)&buf[OF_AH + row * APW + kp] = hv;
        *(uint2*)&buf[OF_AL + row * APW + kp] = lv;
    }
}
__device__ __forceinline__ void store_b2(uint32_t* buf, int tid, int ubase,
                                         const float4* r0, const float4* r1)
{
    #pragma unroll
    for (int u = 0; u < 2; u++) {
        const int lin = (ubase + u) * 256 + tid;
        const int kp = lin >> 6, nq = (lin & 63) * 4;
        uint32_t h[4], l[4];
        split2(r0[u].x, r1[u].x, h[0], l[0]);
        split2(r0[u].y, r1[u].y, h[1], l[1]);
        split2(r0[u].z, r1[u].z, h[2], l[2]);
        split2(r0[u].w, r1[u].w, h[3], l[3]);
        uint4 hv; hv.x = h[0]; hv.y = h[1]; hv.z = h[2]; hv.w = h[3];
        uint4 lv; lv.x = l[0]; lv.y = l[1]; lv.z = l[2]; lv.w = l[3];
        *(uint4*)&buf[OF_BH + kp * BPW + nq] = hv;
        *(uint4*)&buf[OF_BL + kp * BPW + nq] = lv;
    }
}

template<bool GELU, bool RES>
__global__ void __launch_bounds__(256) tc_gemm(
    const float* __restrict__ A, const float* __restrict__ Bw,
    const float* __restrict__ bias, const float* __restrict__ res,
    float* __restrict__ C, int Kd, int N,
    long sA, long sB, long sBias, long sC)
{
    extern __shared__ uint32_t smw[];
    const int tid = threadIdx.x, wid = tid >> 5, lane = tid & 31;
    const int g = lane >> 2, t = lane & 3;
    const int wm = wid & 1, wn = wid >> 1;
    const int bz = blockIdx.z;
    A += (long)bz * sA; Bw += (long)bz * sB; bias += (long)bz * sBias;
    C += (long)bz * sC;
    const int m0 = blockIdx.y * 128, n0 = blockIdx.x * 256;
    const int NT = Kd >> 5;

    float acc[4][8][4];
    #pragma unroll
    for (int mt = 0; mt < 4; mt++)
        #pragma unroll
        for (int nt = 0; nt < 8; nt++)
            #pragma unroll
            for (int c = 0; c < 4; c++) acc[mt][nt][c] = 0.0f;

    {
        float4 ra[4];
        #pragma unroll
        for (int i = 0; i < 4; i++) {
            const int lin = i * 256 + tid;
            const int row = lin >> 3, kq = (lin & 7) * 4;
            ra[i] = *(const float4*)(A + (long)(m0 + row) * Kd + kq);
        }
        store_a(smw, tid, ra);
        float4 r0[2], r1[2];
        #pragma unroll
        for (int ub = 0; ub < 4; ub += 2) {
            #pragma unroll
            for (int u = 0; u < 2; u++) {
                const int lin = (ub + u) * 256 + tid;
                const int kp = lin >> 6, nq = (lin & 63) * 4;
                r0[u] = *(const float4*)(Bw + (long)(2 * kp)     * N + n0 + nq);
                r1[u] = *(const float4*)(Bw + (long)(2 * kp + 1) * N + n0 + nq);
            }
            store_b2(smw, tid, ub, r0, r1);
        }
    }
    __syncthreads();

    for (int kt = 0; kt < NT; kt++) {
        const uint32_t* buf = smw + (kt & 1) * BUFW;
        uint32_t* nbuf = smw + ((kt + 1) & 1) * BUFW;
        const bool pf = (kt + 1 < NT);
        const int kb = (kt + 1) << 5;

        float4 ra[4], r0[2], r1[2];
        if (pf) {
            #pragma unroll
            for (int i = 0; i < 4; i++) {
                const int lin = i * 256 + tid;
                const int row = lin >> 3, kq = (lin & 7) * 4;
                ra[i] = *(const float4*)(A + (long)(m0 + row) * Kd + kb + kq);
            }
            #pragma unroll
            for (int u = 0; u < 2; u++) {
                const int lin = u * 256 + tid;
                const int kp = lin >> 6, nq = (lin & 63) * 4;
                r0[u] = *(const float4*)(Bw + (long)(kb + 2 * kp)     * N + n0 + nq);
                r1[u] = *(const float4*)(Bw + (long)(kb + 2 * kp + 1) * N + n0 + nq);
            }
        }

        kslice_mma(buf, 0, wm, wn, g, t, acc);

        if (pf) {
            store_a(nbuf, tid, ra);
            store_b2(nbuf, tid, 0, r0, r1);
            #pragma unroll
            for (int u = 0; u < 2; u++) {
                const int lin = (2 + u) * 256 + tid;
                const int kp = lin >> 6, nq = (lin & 63) * 4;
                r0[u] = *(const float4*)(Bw + (long)(kb + 2 * kp)     * N + n0 + nq);
                r1[u] = *(const float4*)(Bw + (long)(kb + 2 * kp + 1) * N + n0 + nq);
            }
        }

        kslice_mma(buf, 8, wm, wn, g, t, acc);

        if (pf) store_b2(nbuf, tid, 2, r0, r1);
        __syncthreads();
    }

    #pragma unroll
    for (int mt = 0; mt < 4; mt++) {
        const int row = m0 + wm * 64 + mt * 16 + g;
        #pragma unroll
        for (int nt = 0; nt < 8; nt++) {
            const int col = n0 + wn * 64 + nt * 8 + t * 2;
            const float b0v = bias[col], b1v = bias[col + 1];
            float v0 = acc[mt][nt][0] + b0v;
            float v1 = acc[mt][nt][1] + b1v;
            float v2 = acc[mt][nt][2] + b0v;
            float v3 = acc[mt][nt][3] + b1v;
            if (GELU) {
                v0 *= normcdff(v0); v1 *= normcdff(v1);
                v2 *= normcdff(v2); v3 *= normcdff(v3);
            }
            const long o0 = (long)row * N + col;
            const long o1 = (long)(row + 8) * N + col;
            if (RES) {
                const float2 r0 = *(const float2*)&res[o0];
                const float2 r1 = *(const float2*)&res[o1];
                v0 += r0.x; v1 += r0.y; v2 += r1.x; v3 += r1.y;
            }
            float2 w0; w0.x = v0; w0.y = v1;
            float2 w1; w1.x = v2; w1.y = v3;
            *(float2*)&C[o0] = w0;
            *(float2*)&C[o1] = w1;
        }
    }
}

// ---------------- V transpose: vt[b][h][hd][s] = v[b*S+s][h*64+hd] ---------
__global__ void __launch_bounds__(256) transpose_v(const float* __restrict__ v,
                                                   float* __restrict__ vt)
{
    __shared__ float tile[32][33];
    const int bh = blockIdx.z;          // b*H + h
    const int b = bh >> 4, h = bh & 15;
    const int s0 = blockIdx.x * 32, d0 = blockIdx.y * 32;
    const int tx = threadIdx.x & 31, ty = threadIdx.x >> 5;
    #pragma unroll
    for (int i = 0; i < 32; i += 8)
        tile[ty + i][tx] = v[(long)(b * S_ + s0 + ty + i) * D_ + h * 64 + d0 + tx];
    __syncthreads();
    #pragma unroll
    for (int i = 0; i < 32; i += 8)
        vt[((long)bh * 64 + d0 + ty + i) * S_ + s0 + tx] = tile[tx][ty + i];
}

// ---------------- Flash attention, bf16x3 tensor cores ---------------------
// CTA: 128 queries x one (b,h). 8 warps x 16 q-rows. K-tiles of 64 keys.
// smem u16 layout: Qh[128*72] Ql Kh[64*72] Kl Vh[64*72] Vl + mask bytes
#define QP 72
#define SM_QH 0
#define SM_QL (128 * QP)
#define SM_KH (2 * 128 * QP)
#define SM_KL (SM_KH + 64 * QP)
#define SM_VH (SM_KL + 64 * QP)
#define SM_VL (SM_VH + 64 * QP)
#define SM_END (SM_VL + 64 * QP)          // 36864 u16
#define ATT_SMEM (SM_END * 2 + 128)

__global__ void __launch_bounds__(256) attn_mma(
    const float* __restrict__ qg, const float* __restrict__ kg,
    const float* __restrict__ vtg, const unsigned char* __restrict__ maskg,
    float* __restrict__ og)
{
    extern __shared__ uint16_t sm16[];
    char* ms = (char*)(sm16 + SM_END);

    const int b = blockIdx.z, h = blockIdx.y, q0 = blockIdx.x * 128;
    const int tid = threadIdx.x, wq = tid >> 5, lane = tid & 31;
    const int g = lane >> 2, t4 = lane & 3;
    const float NEG = -3.402823466e38f;

    // ---- load Q tile (128x64) -> split planes ----
    #pragma unroll
    for (int i = 0; i < 8; i++) {
        const int lin = i * 256 + tid;
        const int row = lin >> 4, c4 = (lin & 15) * 4;
        const float4 v = *(const float4*)&qg[(long)(b * S_ + q0 + row) * D_ + h * 64 + c4];
        uint32_t h0, l0, h1, l1;
        split2(v.x, v.y, h0, l0);
        split2(v.z, v.w, h1, l1);
        uint2 hv; hv.x = h0; hv.y = h1;
        uint2 lv; lv.x = l0; lv.y = l1;
        *(uint2*)&sm16[SM_QH + row * QP + c4] = hv;
        *(uint2*)&sm16[SM_QL + row * QP + c4] = lv;
    }
    __syncthreads();

    // ---- extract Q fragments (ktile-invariant) ----
    uint32_t qfh[4][4], qfl[4][4];
    {
        const int qr = wq * 16 + g;
        #pragma unroll
        for (int ks = 0; ks < 4; ks++) {
            const int kc = ks * 16 + 2 * t4;
            qfh[ks][0] = *(const uint32_t*)&sm16[SM_QH + qr * QP + kc];
            qfh[ks][1] = *(const uint32_t*)&sm16[SM_QH + (qr + 8) * QP + kc];
            qfh[ks][2] = *(const uint32_t*)&sm16[SM_QH + qr * QP + kc + 8];
            qfh[ks][3] = *(const uint32_t*)&sm16[SM_QH + (qr + 8) * QP + kc + 8];
            qfl[ks][0] = *(const uint32_t*)&sm16[SM_QL + qr * QP + kc];
            qfl[ks][1] = *(const uint32_t*)&sm16[SM_QL + (qr + 8) * QP + kc];
            qfl[ks][2] = *(const uint32_t*)&sm16[SM_QL + qr * QP + kc + 8];
            qfl[ks][3] = *(const uint32_t*)&sm16[SM_QL + (qr + 8) * QP + kc + 8];
        }
    }

    float m[2], l[2], oacc[8][4];
    m[0] = m[1] = NEG; l[0] = l[1] = 0.0f;
    #pragma unroll
    for (int j = 0; j < 8; j++)
        #pragma unroll
        for (int c = 0; c < 4; c++) oacc[j][c] = 0.0f;

    for (int kt = 0; kt < 32; kt++) {
        const int k0 = kt * 64;
        __syncthreads();   // previous compute done before overwriting K/V smem
        // ---- load K tile (64 keys x 64 hd) and Vt tile (64 hd x 64 keys) ----
        #pragma unroll
        for (int i = 0; i < 4; i++) {
            const int lin = i * 256 + tid;
            const int row = lin >> 4, c4 = (lin & 15) * 4;
            const float4 kv = *(const float4*)&kg[(long)(b * S_ + k0 + row) * D_ + h * 64 + c4];
            const float4 vv = *(const float4*)&vtg[((long)(b * 16 + h) * 64 + row) * S_ + k0 + c4];
            uint32_t h0, l0, h1, l1;
            split2(kv.x, kv.y, h0, l0);
            split2(kv.z, kv.w, h1, l1);
            uint2 a; a.x = h0; a.y = h1;
            uint2 c; c.x = l0; c.y = l1;
            *(uint2*)&sm16[SM_KH + row * QP + c4] = a;
            *(uint2*)&sm16[SM_KL + row * QP + c4] = c;
            split2(vv.x, vv.y, h0, l0);
            split2(vv.z, vv.w, h1, l1);
            a.x = h0; a.y = h1;
            c.x = l0; c.y = l1;
            *(uint2*)&sm16[SM_VH + row * QP + c4] = a;
            *(uint2*)&sm16[SM_VL + row * QP + c4] = c;
        }
        if (tid < 64) ms[tid] = (char)maskg[b * S_ + k0 + tid];
        __syncthreads();

        // ---- scores S = Q K^T (bf16x3) ----
        float sacc[8][4];
        #pragma unroll
        for (int j = 0; j < 8; j++)
            #pragma unroll
            for (int c = 0; c < 4; c++) sacc[j][c] = 0.0f;

        #pragma unroll
        for (int j = 0; j < 8; j++) {
            const int krow = (8 * j + g) * QP;
            #pragma unroll
            for (int ks = 0; ks < 4; ks++) {
                const int kc = ks * 16 + 2 * t4;
                const uint32_t bh0 = *(const uint32_t*)&sm16[SM_KH + krow + kc];
                const uint32_t bh1 = *(const uint32_t*)&sm16[SM_KH + krow + kc + 8];
                const uint32_t bl0 = *(const uint32_t*)&sm16[SM_KL + krow + kc];
                const uint32_t bl1 = *(const uint32_t*)&sm16[SM_KL + krow + kc + 8];
                mma16(sacc[j], qfh[ks][0], qfh[ks][1], qfh[ks][2], qfh[ks][3], bh0, bh1);
                mma16(sacc[j], qfh[ks][0], qfh[ks][1], qfh[ks][2], qfh[ks][3], bl0, bl1);
                mma16(sacc[j], qfl[ks][0], qfl[ks][1], qfl[ks][2], qfl[ks][3], bh0, bh1);
            }
        }

        // ---- scale + mask ----
        #pragma unroll
        for (int j = 0; j < 8; j++) {
            const int col = 8 * j + 2 * t4;
            const bool m0k = ms[col] != 0;
            const bool m1k = ms[col + 1] != 0;
            sacc[j][0] = m0k ? NEG : sacc[j][0] * 0.125f;
            sacc[j][1] = m1k ? NEG : sacc[j][1] * 0.125f;
            sacc[j][2] = m0k ? NEG : sacc[j][2] * 0.125f;
            sacc[j][3] = m1k ? NEG : sacc[j][3] * 0.125f;
        }

        // ---- online softmax (rows g and g+8; quad = lanes sharing g) ----
        #pragma unroll
        for (int r = 0; r < 2; r++) {
            float rmax = NEG;
            #pragma unroll
            for (int j = 0; j < 8; j++) {
                rmax = fmaxf(rmax, sacc[j][2 * r]);
                rmax = fmaxf(rmax, sacc[j][2 * r + 1]);
            }
            rmax = fmaxf(rmax, __shfl_xor_sync(0xffffffffu, rmax, 1));
            rmax = fmaxf(rmax, __shfl_xor_sync(0xffffffffu, rmax, 2));
            const float mnew = fmaxf(m[r], rmax);
            const float corr = expf(m[r] - mnew);
            float rsum = 0.0f;
            #pragma unroll
            for (int j = 0; j < 8; j++) {
                float p0 = expf(sacc[j][2 * r]     - mnew);
                float p1 = expf(sacc[j][2 * r + 1] - mnew);
                sacc[j][2 * r] = p0; sacc[j][2 * r + 1] = p1;
                rsum += p0 + p1;
            }
            rsum += __shfl_xor_sync(0xffffffffu, rsum, 1);
            rsum += __shfl_xor_sync(0xffffffffu, rsum, 2);
            l[r] = l[r] * corr + rsum;
            m[r] = mnew;
            #pragma unroll
            for (int j = 0; j < 8; j++) {
                oacc[j][2 * r]     *= corr;
                oacc[j][2 * r + 1] *= corr;
            }
        }

        // ---- O += P V (P frags from score regs, bf16x3) ----
        #pragma unroll
        for (int ks = 0; ks < 4; ks++) {
            const int j0 = 2 * ks, j1 = 2 * ks + 1;
            uint32_t ph0, pl0, ph1, pl1, ph2, pl2, ph3, pl3;
            split2(sacc[j0][0], sacc[j0][1], ph0, pl0);
            split2(sacc[j0][2], sacc[j0][3], ph1, pl1);
            split2(sacc[j1][0], sacc[j1][1], ph2, pl2);
            split2(sacc[j1][2], sacc[j1][3], ph3, pl3);
            const int kc = ks * 16 + 2 * t4;
            #pragma unroll
            for (int j = 0; j < 8; j++) {
                const int vrow = (8 * j + g) * QP;
                const uint32_t vh0 = *(const uint32_t*)&sm16[SM_VH + vrow + kc];
                const uint32_t vh1 = *(const uint32_t*)&sm16[SM_VH + vrow + kc + 8];
                const uint32_t vl0 = *(const uint32_t*)&sm16[SM_VL + vrow + kc];
                const uint32_t vl1 = *(const uint32_t*)&sm16[SM_VL + vrow + kc + 8];
                mma16(oacc[j], ph0, ph1, ph2, ph3, vh0, vh1);
                mma16(oacc[j], ph0, ph1, ph2, ph3, vl0, vl1);
                mma16(oacc[j], pl0, pl1, pl2, pl3, vh0, vh1);
            }
        }
    }

    // ---- epilogue: divide by l, store ----
    const float inv0 = 1.0f / l[0], inv1 = 1.0f / l[1];
    const int row0 = q0 + wq * 16 + g;
    #pragma unroll
    for (int j = 0; j < 8; j++) {
        const int col = h * 64 + 8 * j + 2 * t4;
        float2 w0; w0.x = oacc[j][0] * inv0; w0.y = oacc[j][1] * inv0;
        float2 w1; w1.x = oacc[j][2] * inv1; w1.y = oacc[j][3] * inv1;
        *(float2*)&og[(long)(b * S_ + row0) * D_ + col] = w0;
        *(float2*)&og[(long)(b * S_ + row0 + 8) * D_ + col] = w1;
    }
}

// ---------------- LayerNorm -----------------------------------------------
__global__ void __launch_bounds__(256) ln_kernel(const float* __restrict__ x,
                                                 const float* __restrict__ g,
                                                 const float* __restrict__ b,
                                                 float* __restrict__ out)
{
    const int row = blockIdx.x;
    const int tid = threadIdx.x;
    const float4 v = ((const float4*)(x + (long)row * D_))[tid];

    __shared__ float red[256];
    __shared__ float s_mu, s_rstd;

    float s = v.x + v.y + v.z + v.w;
    red[tid] = s; __syncthreads();
    for (int o = 128; o > 0; o >>= 1) {
        if (tid < o) red[tid] += red[tid + o];
        __syncthreads();
    }
    if (tid == 0) s_mu = red[0] * (1.0f / D_);
    __syncthreads();
    const float mu = s_mu;

    float dx0 = v.x - mu, dx1 = v.y - mu, dx2 = v.z - mu, dx3 = v.w - mu;
    float sq = dx0*dx0 + dx1*dx1 + dx2*dx2 + dx3*dx3;
    red[tid] = sq; __syncthreads();
    for (int o = 128; o > 0; o >>= 1) {
        if (tid < o) red[tid] += red[tid + o];
        __syncthreads();
    }
    if (tid == 0) s_rstd = rsqrtf(red[0] * (1.0f / D_) + 1e-5f);
    __syncthreads();
    const float rstd = s_rstd;

    const float4 gg = ((const float4*)g)[tid];
    const float4 bb = ((const float4*)b)[tid];
    float4 o4;
    o4.x = dx0 * rstd * gg.x + bb.x;
    o4.y = dx1 * rstd * gg.y + bb.y;
    o4.z = dx2 * rstd * gg.z + bb.z;
    o4.w = dx3 * rstd * gg.w + bb.w;
    ((float4*)(out + (long)row * D_))[tid] = o4;
}

// ---------------- Router --------------------------------------------------
__global__ void __launch_bounds__(256) router_kernel(
    const float* __restrict__ xn, const float* __restrict__ wr,
    int* __restrict__ eidx, float* __restrict__ gate)
{
    const int warp = threadIdx.x >> 5, lane = threadIdx.x & 31;
    const int t = blockIdx.x * 8 + warp;
    const float* xr = xn + (long)t * D_;

    float a[E_];
    #pragma unroll
    for (int e = 0; e < E_; e++) a[e] = 0.0f;
    for (int d = lane; d < D_; d += 32) {
        const float xv = xr[d];
        const float* w = wr + d * E_;
        #pragma unroll
        for (int e = 0; e < E_; e++) a[e] += xv * w[e];
    }
    #pragma unroll
    for (int e = 0; e < E_; e++)
        #pragma unroll
        for (int o = 16; o > 0; o >>= 1)
            a[e] += __shfl_xor_sync(0xffffffffu, a[e], o);

    if (lane == 0) {
        float mx = a[0];
        #pragma unroll
        for (int e = 1; e < E_; e++) mx = fmaxf(mx, a[e]);
        float ex[E_];
        #pragma unroll
        for (int e = 0; e < E_; e++) ex[e] = expf(a[e] - mx);
        int i0 = 0; float v0 = ex[0];
        #pragma unroll
        for (int e = 1; e < E_; e++) if (ex[e] > v0) { v0 = ex[e]; i0 = e; }
        int i1 = -1; float v1 = -1.0f;
        #pragma unroll
        for (int e = 0; e < E_; e++)
            if (e != i0 && ex[e] > v1) { v1 = ex[e]; i1 = e; }
        const float inv = 1.0f / (v0 + v1);
        eidx[t]       = i0; gate[t]       = v0 * inv;
        eidx[T_ + t]  = i1; gate[T_ + t]  = v1 * inv;
    }
}

// ---------------- Slot-major capacity scan --------------------------------
__global__ void __launch_bounds__(256) scan_kernel(const int* __restrict__ eidx,
                                                   int* __restrict__ pos)
{
    const int e = blockIdx.x;
    __shared__ int sd[256];
    int base = 0;
    for (int c = 0; c < KT_; c += 256) {
        const int i = c + threadIdx.x;
        const int flag = (eidx[i] == e) ? 1 : 0;
        sd[threadIdx.x] = flag;
        __syncthreads();
        for (int o = 1; o < 256; o <<= 1) {
            int v = (threadIdx.x >= o) ? sd[threadIdx.x - o] : 0;
            __syncthreads();
            sd[threadIdx.x] += v;
            __syncthreads();
        }
        if (flag) pos[i] = base + sd[threadIdx.x] - 1;
        base += sd[255];
        __syncthreads();
    }
}

__global__ void __launch_bounds__(256) zero_kernel(float4* __restrict__ p, int n4)
{
    const int i = blockIdx.x * 256 + threadIdx.x;
    if (i < n4) p[i] = make_float4(0.f, 0.f, 0.f, 0.f);
}

__global__ void __launch_bounds__(256) dispatch_kernel(
    const float* __restrict__ xn, const int* __restrict__ eidx,
    const int* __restrict__ pos, float* __restrict__ disp)
{
    const int s = blockIdx.x;
    const int p = pos[s];
    if (p >= CAP_) return;
    const int e = eidx[s];
    const int t = s & (T_ - 1);
    const float4* src = (const float4*)(xn + (long)t * D_);
    float4* dst = (float4*)(disp + ((long)e * CAP_ + p) * D_);
    dst[threadIdx.x] = src[threadIdx.x];
}

__global__ void __launch_bounds__(256) combine_kernel(
    const float* __restrict__ x2, const float* __restrict__ shout,
    const float* __restrict__ eo, const int* __restrict__ eidx,
    const int* __restrict__ pos, const float* __restrict__ gate,
    float* __restrict__ out)
{
    const int t = blockIdx.x;
    const int p0 = pos[t], p1 = pos[T_ + t];
    const float g0 = gate[t]      * (p0 < CAP_ ? 1.0f : 0.0f);
    const float g1 = gate[T_ + t] * (p1 < CAP_ ? 1.0f : 0.0f);
    const long o0 = ((long)eidx[t]      * CAP_ + min(p0, CAP_ - 1)) * D_;
    const long o1 = ((long)eidx[T_ + t] * CAP_ + min(p1, CAP_ - 1)) * D_;

    const int c = threadIdx.x;
    float4 a = ((const float4*)(x2 + (long)t * D_))[c];
    float4 s = ((const float4*)(shout + (long)t * D_))[c];
    float4 r0 = ((const float4*)(eo + o0))[c];
    float4 r1 = ((const float4*)(eo + o1))[c];
    float4 o;
    o.x = a.x + s.x + g0 * r0.x + g1 * r1.x;
    o.y = a.y + s.y + g0 * r0.y + g1 * r1.y;
    o.z = a.z + s.z + g0 * r0.z + g1 * r1.z;
    o.w = a.w + s.w + g0 * r0.w + g1 * r1.w;
    ((float4*)(out + (long)t * D_))[c] = o;
}

// ---------------------------------------------------------------------------
extern "C" void kernel_launch(void* const* d_in, const int* in_sizes, int n_in,
                              void* d_out, int out_size)
{
    const float* x   = (const float*)d_in[0];
    const unsigned char* mask = (const unsigned char*)d_in[1];
    const float* ln1g = (const float*)d_in[2];
    const float* ln1b = (const float*)d_in[3];
    const float* wq = (const float*)d_in[4];  const float* bq = (const float*)d_in[5];
    const float* wk = (const float*)d_in[6];  const float* bk = (const float*)d_in[7];
    const float* wv = (const float*)d_in[8];  const float* bv = (const float*)d_in[9];
    const float* wo = (const float*)d_in[10]; const float* bo = (const float*)d_in[11];
    const float* ln2g = (const float*)d_in[12];
    const float* ln2b = (const float*)d_in[13];
    const float* wr = (const float*)d_in[14];
    const float* w1 = (const float*)d_in[15]; const float* b1 = (const float*)d_in[16];
    const float* w2 = (const float*)d_in[17]; const float* b2 = (const float*)d_in[18];
    const float* ws1 = (const float*)d_in[19]; const float* bs1 = (const float*)d_in[20];
    const float* ws2 = (const float*)d_in[21]; const float* bs2 = (const float*)d_in[22];
    float* out = (float*)d_out;

    float *xn1, *q, *k, *v, *vt, *attn, *x2, *xn2, *disp, *hb, *eo, *shh, *shout, *gate;
    int *eidx, *pos;
    cudaGetSymbolAddress((void**)&xn1,  g_xn1);
    cudaGetSymbolAddress((void**)&q,    g_q);
    cudaGetSymbolAddress((void**)&k,    g_k);
    cudaGetSymbolAddress((void**)&v,    g_v);
    cudaGetSymbolAddress((void**)&vt,   g_vt);
    cudaGetSymbolAddress((void**)&attn, g_attn);
    cudaGetSymbolAddress((void**)&x2,   g_x2);
    cudaGetSymbolAddress((void**)&xn2,  g_xn2);
    cudaGetSymbolAddress((void**)&disp, g_disp);
    cudaGetSymbolAddress((void**)&hb,   g_h);
    cudaGetSymbolAddress((void**)&eo,   g_eo);
    cudaGetSymbolAddress((void**)&shh,  g_shh);
    cudaGetSymbolAddress((void**)&shout,g_shout);
    cudaGetSymbolAddress((void**)&eidx, g_eidx);
    cudaGetSymbolAddress((void**)&pos,  g_pos);
    cudaGetSymbolAddress((void**)&gate, g_gate);

    cudaFuncSetAttribute(attn_mma,
                         cudaFuncAttributeMaxDynamicSharedMemorySize, ATT_SMEM);
    cudaFuncSetAttribute(tc_gemm<false, false>,
                         cudaFuncAttributeMaxDynamicSharedMemorySize, TC_SMEM);
    cudaFuncSetAttribute(tc_gemm<false, true>,
                         cudaFuncAttributeMaxDynamicSharedMemorySize, TC_SMEM);
    cudaFuncSetAttribute(tc_gemm<true, false>,
                         cudaFuncAttributeMaxDynamicSharedMemorySize, TC_SMEM);

    // 1) LN1
    ln_kernel<<<T_, 256>>>(x, ln1g, ln1b, xn1);

    // 2) QKV projections (bf16x3 tensor cores)
    dim3 gDD(D_ / 256, T_ / 128, 1);
    tc_gemm<false, false><<<gDD, 256, TC_SMEM>>>(xn1, wq, bq, nullptr, q, D_, D_, 0, 0, 0, 0);
    tc_gemm<false, false><<<gDD, 256, TC_SMEM>>>(xn1, wk, bk, nullptr, k, D_, D_, 0, 0, 0, 0);
    tc_gemm<false, false><<<gDD, 256, TC_SMEM>>>(xn1, wv, bv, nullptr, v, D_, D_, 0, 0, 0, 0);

    // 3) attention (tensor cores); V transposed per-(b,h) first
    transpose_v<<<dim3(S_ / 32, 2, B_ * H_), 256>>>(v, vt);
    attn_mma<<<dim3(S_ / 128, H_, B_), 256, ATT_SMEM>>>(q, k, vt, mask, attn);

    // 4) O projection + residual -> x2
    tc_gemm<false, true><<<gDD, 256, TC_SMEM>>>(attn, wo, bo, x, x2, D_, D_, 0, 0, 0, 0);

    // 5) LN2
    ln_kernel<<<T_, 256>>>(x2, ln2g, ln2b, xn2);

    // 6) router + slot-major capacity scan
    router_kernel<<<T_ / 8, 256>>>(xn2, wr, eidx, gate);
    scan_kernel<<<E_, 256>>>(eidx, pos);

    // 7) dispatch
    const int n4 = E_ * CAP_ * D_ / 4;
    zero_kernel<<<(n4 + 255) / 256, 256>>>((float4*)disp, n4);
    dispatch_kernel<<<KT_, 256>>>(xn2, eidx, pos, disp);

    // 8) expert FFN (batched over blockIdx.z = expert)
    tc_gemm<true, false><<<dim3(F_ / 256, CAP_ / 128, E_), 256, TC_SMEM>>>(
        disp, w1, b1, nullptr, hb, D_, F_,
        (long)CAP_ * D_, (long)D_ * F_, (long)F_, (long)CAP_ * F_);
    tc_gemm<false, false><<<dim3(D_ / 256, CAP_ / 128, E_), 256, TC_SMEM>>>(
        hb, w2, b2, nullptr, eo, F_, D_,
        (long)CAP_ * F_, (long)F_ * D_, (long)D_, (long)CAP_ * D_);

    // 9) shared expert
    tc_gemm<true, false><<<dim3(FS_ / 256, T_ / 128, 1), 256, TC_SMEM>>>(
        xn2, ws1, bs1, nullptr, shh, D_, FS_, 0, 0, 0, 0);
    tc_gemm<false, false><<<dim3(D_ / 256, T_ / 128, 1), 256, TC_SMEM>>>(
        shh, ws2, bs2, nullptr, shout, FS_, D_, 0, 0, 0, 0);

    // 10) combine + residuals -> out
    combine_kernel<<<T_, 256>>>(x2, shout, eo, eidx, pos, gate, out);
}